// round 1
// baseline (speedup 1.0000x reference)
#include <cuda_runtime.h>
#include <math.h>

// Problem constants
#define EDIM 512
#define NSEQ 4096
#define NHEAD 8
#define HDHEAD 64
#define HDIM 2048

// Scratch (alloc-free rule: __device__ globals)
__device__ float g_h1[NSEQ * EDIM];        // LN1 output
__device__ float g_qkv[NSEQ * 3 * EDIM];   // QKV projections
__device__ float g_attn[NSEQ * EDIM];      // attention output (pre-proj)
__device__ float g_x1[NSEQ * EDIM];        // residual after attention
__device__ float g_h2[NSEQ * EDIM];        // LN2 output
__device__ float g_m1[NSEQ * HDIM];        // fc1 output
__device__ float g_m2[NSEQ * HDIM];        // fc2 output

// ---------------------------------------------------------------------------
// LayerNorm: one block per row, 128 threads, float4 per thread (E=512)
// ---------------------------------------------------------------------------
__global__ void ln_kernel(const float* __restrict__ X, const float* __restrict__ g,
                          const float* __restrict__ b, float* __restrict__ Y) {
    const int row = blockIdx.x;
    const int t = threadIdx.x;  // 128 threads
    const float4* Xv = (const float4*)(X + (size_t)row * EDIM);
    float4 v = Xv[t];

    __shared__ float red[4];
    float s = v.x + v.y + v.z + v.w;
    #pragma unroll
    for (int o = 16; o > 0; o >>= 1) s += __shfl_down_sync(0xffffffffu, s, o);
    if ((t & 31) == 0) red[t >> 5] = s;
    __syncthreads();
    float mean = (red[0] + red[1] + red[2] + red[3]) * (1.0f / EDIM);
    __syncthreads();

    float dx = v.x - mean, dy = v.y - mean, dz = v.z - mean, dw = v.w - mean;
    float s2 = dx * dx + dy * dy + dz * dz + dw * dw;
    #pragma unroll
    for (int o = 16; o > 0; o >>= 1) s2 += __shfl_down_sync(0xffffffffu, s2, o);
    if ((t & 31) == 0) red[t >> 5] = s2;
    __syncthreads();
    float var = (red[0] + red[1] + red[2] + red[3]) * (1.0f / EDIM);
    float rs = rsqrtf(var + 1e-5f);

    float4 gv = ((const float4*)g)[t];
    float4 bv = ((const float4*)b)[t];
    float4 o4;
    o4.x = dx * rs * gv.x + bv.x;
    o4.y = dy * rs * gv.y + bv.y;
    o4.z = dz * rs * gv.z + bv.z;
    o4.w = dw * rs * gv.w + bv.w;
    ((float4*)(Y + (size_t)row * EDIM))[t] = o4;
}

// ---------------------------------------------------------------------------
// SGEMM: C[M,N] = A[M,K] * B[N,K]^T + bias (+ residual) (+ relu)
// Both A and B are K-contiguous. 128x128x8 tile, 256 threads, 8x8 per thread.
// ---------------------------------------------------------------------------
template <bool RELU, bool RES>
__global__ void __launch_bounds__(256, 2)
sgemm_kernel(const float* __restrict__ A, const float* __restrict__ B,
             const float* __restrict__ bias, const float* __restrict__ Rs,
             float* __restrict__ C, int M, int N, int K) {
    __shared__ float As[8][128];
    __shared__ float Bs[8][128];

    const int t = threadIdx.x;
    const int mBase = blockIdx.y * 128;
    const int nBase = blockIdx.x * 128;

    const int lr = t >> 1;         // 0..127 (row within tile for loads)
    const int lc = (t & 1) * 4;    // 0 or 4 (k offset for loads)
    const float* Aptr = A + (size_t)(mBase + lr) * K + lc;
    const float* Bptr = B + (size_t)(nBase + lr) * K + lc;

    const int tr = (t >> 4) * 8;   // output row offset within tile
    const int tc = (t & 15) * 8;   // output col offset within tile

    float acc[8][8];
    #pragma unroll
    for (int i = 0; i < 8; i++)
        #pragma unroll
        for (int j = 0; j < 8; j++) acc[i][j] = 0.0f;

    for (int k0 = 0; k0 < K; k0 += 8) {
        float4 a4 = *(const float4*)(Aptr + k0);
        float4 b4 = *(const float4*)(Bptr + k0);
        As[lc + 0][lr] = a4.x; As[lc + 1][lr] = a4.y;
        As[lc + 2][lr] = a4.z; As[lc + 3][lr] = a4.w;
        Bs[lc + 0][lr] = b4.x; Bs[lc + 1][lr] = b4.y;
        Bs[lc + 2][lr] = b4.z; Bs[lc + 3][lr] = b4.w;
        __syncthreads();

        #pragma unroll
        for (int kk = 0; kk < 8; kk++) {
            float4 ra0 = *(const float4*)&As[kk][tr];
            float4 ra1 = *(const float4*)&As[kk][tr + 4];
            float4 rb0 = *(const float4*)&Bs[kk][tc];
            float4 rb1 = *(const float4*)&Bs[kk][tc + 4];
            float ra[8] = {ra0.x, ra0.y, ra0.z, ra0.w, ra1.x, ra1.y, ra1.z, ra1.w};
            float rb[8] = {rb0.x, rb0.y, rb0.z, rb0.w, rb1.x, rb1.y, rb1.z, rb1.w};
            #pragma unroll
            for (int i = 0; i < 8; i++)
                #pragma unroll
                for (int j = 0; j < 8; j++)
                    acc[i][j] = fmaf(ra[i], rb[j], acc[i][j]);
        }
        __syncthreads();
    }

    // Epilogue
    #pragma unroll
    for (int i = 0; i < 8; i++) {
        const int row = mBase + tr + i;
        float* crow = C + (size_t)row * N + nBase + tc;
        const float* rrow = RES ? (Rs + (size_t)row * N + nBase + tc) : nullptr;
        #pragma unroll
        for (int j4 = 0; j4 < 8; j4 += 4) {
            float4 o;
            float* op = &o.x;
            #pragma unroll
            for (int j = 0; j < 4; j++) {
                float c = acc[i][j4 + j] + bias[nBase + tc + j4 + j];
                if (RES) c += rrow[j4 + j];
                if (RELU) c = fmaxf(c, 0.0f);
                op[j] = c;
            }
            *(float4*)(crow + j4) = o;
        }
    }
}

// ---------------------------------------------------------------------------
// Flash attention: one block per (head, 64-query block). 256 threads.
// qkv layout per token row (1536): [s(3)][h(8)][d(64)]
// ---------------------------------------------------------------------------
__global__ void __launch_bounds__(256, 2)
attn_kernel(const float* __restrict__ qkv, float* __restrict__ out) {
    extern __shared__ float sm[];
    float* Qs = sm;                 // 64 x 65
    float* Ks = Qs + 64 * 65;       // 64 x 65
    float* Ss = Ks + 64 * 65;       // 64 x 65
    float* Vs = Ss + 64 * 65;       // 64 x 64
    float* rowM = Vs + 64 * 64;     // 64
    float* rowL = rowM + 64;        // 64
    float* rowA = rowL + 64;        // 64

    const int t = threadIdx.x;      // 256
    const int h = blockIdx.y;
    const int qb = blockIdx.x * 64;
    const float scale = 0.125f;     // 1/sqrt(64)

    // Load Q tile (scaled)
    for (int idx = t; idx < 64 * 64; idx += 256) {
        int r = idx >> 6, d = idx & 63;
        Qs[r * 65 + d] = qkv[(size_t)(qb + r) * 1536 + h * 64 + d] * scale;
    }
    if (t < 64) { rowM[t] = -1e30f; rowL[t] = 0.0f; }

    const int ty = t >> 4, tx = t & 15;
    const int r0 = ty * 4, c0 = tx * 4;
    float acc[4][4] = {};

    for (int kb = 0; kb < NSEQ; kb += 64) {
        __syncthreads();  // previous iteration done reading Ks/Vs/Ss (also covers Q load)
        for (int idx = t; idx < 64 * 64; idx += 256) {
            int r = idx >> 6, d = idx & 63;
            const float* base = qkv + (size_t)(kb + r) * 1536 + h * 64 + d;
            Ks[r * 65 + d] = base[512];
            Vs[idx]        = base[1024];
        }
        __syncthreads();

        // S = Q * K^T  (each thread: 4x4)
        float s[4][4] = {};
        #pragma unroll 4
        for (int d = 0; d < 64; d++) {
            float q0 = Qs[(r0 + 0) * 65 + d], q1 = Qs[(r0 + 1) * 65 + d];
            float q2 = Qs[(r0 + 2) * 65 + d], q3 = Qs[(r0 + 3) * 65 + d];
            float k0 = Ks[(c0 + 0) * 65 + d], k1 = Ks[(c0 + 1) * 65 + d];
            float k2 = Ks[(c0 + 2) * 65 + d], k3 = Ks[(c0 + 3) * 65 + d];
            s[0][0] = fmaf(q0, k0, s[0][0]); s[0][1] = fmaf(q0, k1, s[0][1]);
            s[0][2] = fmaf(q0, k2, s[0][2]); s[0][3] = fmaf(q0, k3, s[0][3]);
            s[1][0] = fmaf(q1, k0, s[1][0]); s[1][1] = fmaf(q1, k1, s[1][1]);
            s[1][2] = fmaf(q1, k2, s[1][2]); s[1][3] = fmaf(q1, k3, s[1][3]);
            s[2][0] = fmaf(q2, k0, s[2][0]); s[2][1] = fmaf(q2, k1, s[2][1]);
            s[2][2] = fmaf(q2, k2, s[2][2]); s[2][3] = fmaf(q2, k3, s[2][3]);
            s[3][0] = fmaf(q3, k0, s[3][0]); s[3][1] = fmaf(q3, k1, s[3][1]);
            s[3][2] = fmaf(q3, k2, s[3][2]); s[3][3] = fmaf(q3, k3, s[3][3]);
        }
        #pragma unroll
        for (int i = 0; i < 4; i++)
            #pragma unroll
            for (int j = 0; j < 4; j++)
                Ss[(r0 + i) * 65 + c0 + j] = s[i][j];
        __syncthreads();

        // Online softmax for this tile (64 threads, one per row)
        if (t < 64) {
            float* Sr = Ss + t * 65;
            float mx = rowM[t];
            #pragma unroll 8
            for (int j = 0; j < 64; j++) mx = fmaxf(mx, Sr[j]);
            float al = __expf(rowM[t] - mx);
            float sum = 0.0f;
            #pragma unroll 8
            for (int j = 0; j < 64; j++) {
                float p = __expf(Sr[j] - mx);
                Sr[j] = p;
                sum += p;
            }
            rowL[t] = rowL[t] * al + sum;
            rowM[t] = mx;
            rowA[t] = al;
        }
        __syncthreads();

        // O = O*alpha + P*V
        float al0 = rowA[r0 + 0], al1 = rowA[r0 + 1], al2 = rowA[r0 + 2], al3 = rowA[r0 + 3];
        #pragma unroll
        for (int j = 0; j < 4; j++) {
            acc[0][j] *= al0; acc[1][j] *= al1; acc[2][j] *= al2; acc[3][j] *= al3;
        }
        #pragma unroll 4
        for (int k = 0; k < 64; k++) {
            float4 v = *(const float4*)&Vs[k * 64 + c0];
            float p0 = Ss[(r0 + 0) * 65 + k], p1 = Ss[(r0 + 1) * 65 + k];
            float p2 = Ss[(r0 + 2) * 65 + k], p3 = Ss[(r0 + 3) * 65 + k];
            acc[0][0] = fmaf(p0, v.x, acc[0][0]); acc[0][1] = fmaf(p0, v.y, acc[0][1]);
            acc[0][2] = fmaf(p0, v.z, acc[0][2]); acc[0][3] = fmaf(p0, v.w, acc[0][3]);
            acc[1][0] = fmaf(p1, v.x, acc[1][0]); acc[1][1] = fmaf(p1, v.y, acc[1][1]);
            acc[1][2] = fmaf(p1, v.z, acc[1][2]); acc[1][3] = fmaf(p1, v.w, acc[1][3]);
            acc[2][0] = fmaf(p2, v.x, acc[2][0]); acc[2][1] = fmaf(p2, v.y, acc[2][1]);
            acc[2][2] = fmaf(p2, v.z, acc[2][2]); acc[2][3] = fmaf(p2, v.w, acc[2][3]);
            acc[3][0] = fmaf(p3, v.x, acc[3][0]); acc[3][1] = fmaf(p3, v.y, acc[3][1]);
            acc[3][2] = fmaf(p3, v.z, acc[3][2]); acc[3][3] = fmaf(p3, v.w, acc[3][3]);
        }
    }
    __syncthreads();

    // Normalize + store: out[(qb+r), h*64 + c]
    #pragma unroll
    for (int i = 0; i < 4; i++) {
        float inv = 1.0f / rowL[r0 + i];
        float* orow = out + (size_t)(qb + r0 + i) * EDIM + h * 64 + c0;
        #pragma unroll
        for (int j = 0; j < 4; j++) orow[j] = acc[i][j] * inv;
    }
}

static const int ATTN_SMEM = (3 * 64 * 65 + 64 * 64 + 3 * 64) * sizeof(float);  // 67072 B

extern "C" void kernel_launch(void* const* d_in, const int* in_sizes, int n_in,
                              void* d_out, int out_size) {
    const float* x      = (const float*)d_in[0];
    const float* ln_g   = (const float*)d_in[1];
    const float* ln_b   = (const float*)d_in[2];
    const float* qkv_w  = (const float*)d_in[3];
    const float* qkv_b  = (const float*)d_in[4];
    const float* proj_w = (const float*)d_in[5];
    const float* proj_b = (const float*)d_in[6];
    const float* fc1_w  = (const float*)d_in[7];
    const float* fc1_b  = (const float*)d_in[8];
    const float* fc2_w  = (const float*)d_in[9];
    const float* fc2_b  = (const float*)d_in[10];
    const float* fc3_w  = (const float*)d_in[11];
    const float* fc3_b  = (const float*)d_in[12];
    float* out = (float*)d_out;

    float *h1, *qkvb, *attnb, *x1, *h2, *m1, *m2;
    cudaGetSymbolAddress((void**)&h1, g_h1);
    cudaGetSymbolAddress((void**)&qkvb, g_qkv);
    cudaGetSymbolAddress((void**)&attnb, g_attn);
    cudaGetSymbolAddress((void**)&x1, g_x1);
    cudaGetSymbolAddress((void**)&h2, g_h2);
    cudaGetSymbolAddress((void**)&m1, g_m1);
    cudaGetSymbolAddress((void**)&m2, g_m2);

    cudaFuncSetAttribute(attn_kernel, cudaFuncAttributeMaxDynamicSharedMemorySize, ATTN_SMEM);

    // 1. LN1
    ln_kernel<<<NSEQ, 128>>>(x, ln_g, ln_b, h1);
    // 2. QKV: [4096,512] x [1536,512]^T -> [4096,1536]
    sgemm_kernel<false, false><<<dim3(12, 32), 256>>>(h1, qkv_w, qkv_b, nullptr, qkvb,
                                                      NSEQ, 3 * EDIM, EDIM);
    // 3. Attention
    attn_kernel<<<dim3(64, NHEAD), 256, ATTN_SMEM>>>(qkvb, attnb);
    // 4. proj + residual: x1 = attn @ proj_w^T + b + x
    sgemm_kernel<false, true><<<dim3(4, 32), 256>>>(attnb, proj_w, proj_b, x, x1,
                                                    NSEQ, EDIM, EDIM);
    // 5. LN2
    ln_kernel<<<NSEQ, 128>>>(x1, ln_g, ln_b, h2);
    // 6. fc1 + relu: [4096,512] x [2048,512]^T
    sgemm_kernel<true, false><<<dim3(16, 32), 256>>>(h2, fc1_w, fc1_b, nullptr, m1,
                                                     NSEQ, HDIM, EDIM);
    // 7. fc2 + relu: [4096,2048] x [2048,2048]^T
    sgemm_kernel<true, false><<<dim3(16, 32), 256>>>(m1, fc2_w, fc2_b, nullptr, m2,
                                                     NSEQ, HDIM, HDIM);
    // 8. fc3 + bias + residual -> out
    sgemm_kernel<false, true><<<dim3(4, 32), 256>>>(m2, fc3_w, fc3_b, x1, out,
                                                    NSEQ, EDIM, HDIM);
}

// round 2
// speedup vs baseline: 1.1088x; 1.1088x over previous
#include <cuda_runtime.h>
#include <math.h>

// Problem constants
#define EDIM 512
#define NSEQ 4096
#define NHEAD 8
#define HDIM 2048

typedef unsigned long long u64;

// ---- packed f32x2 helpers (sm_103a FFMA2 path) ----
__device__ __forceinline__ u64 pack2(float v) {
    u64 r; unsigned u = __float_as_uint(v);
    asm("mov.b64 %0, {%1, %1};" : "=l"(r) : "r"(u));
    return r;
}
__device__ __forceinline__ u64 fma2(u64 a, u64 b, u64 c) {
    u64 d;
    asm("fma.rn.f32x2 %0, %1, %2, %3;" : "=l"(d) : "l"(a), "l"(b), "l"(c));
    return d;
}
__device__ __forceinline__ u64 mul2(u64 a, u64 b) {
    u64 d;
    asm("mul.rn.f32x2 %0, %1, %2;" : "=l"(d) : "l"(a), "l"(b));
    return d;
}
__device__ __forceinline__ float2 unpack2(u64 v) {
    unsigned lo, hi;
    asm("mov.b64 {%0, %1}, %2;" : "=r"(lo), "=r"(hi) : "l"(v));
    float2 f; f.x = __uint_as_float(lo); f.y = __uint_as_float(hi);
    return f;
}

// Scratch (alloc-free rule: __device__ globals)
__device__ float g_h1[NSEQ * EDIM];
__device__ float g_qkv[NSEQ * 3 * EDIM];
__device__ float g_attn[NSEQ * EDIM];
__device__ float g_x1[NSEQ * EDIM];
__device__ float g_h2[NSEQ * EDIM];
__device__ float g_m1[NSEQ * HDIM];
__device__ float g_m2[NSEQ * HDIM];

// ---------------------------------------------------------------------------
// LayerNorm: one block per row, 128 threads, float4 per thread (E=512)
// ---------------------------------------------------------------------------
__global__ void ln_kernel(const float* __restrict__ X, const float* __restrict__ g,
                          const float* __restrict__ b, float* __restrict__ Y) {
    const int row = blockIdx.x;
    const int t = threadIdx.x;  // 128 threads
    const float4* Xv = (const float4*)(X + (size_t)row * EDIM);
    float4 v = Xv[t];

    __shared__ float red[4];
    float s = v.x + v.y + v.z + v.w;
    #pragma unroll
    for (int o = 16; o > 0; o >>= 1) s += __shfl_down_sync(0xffffffffu, s, o);
    if ((t & 31) == 0) red[t >> 5] = s;
    __syncthreads();
    float mean = (red[0] + red[1] + red[2] + red[3]) * (1.0f / EDIM);
    __syncthreads();

    float dx = v.x - mean, dy = v.y - mean, dz = v.z - mean, dw = v.w - mean;
    float s2 = dx * dx + dy * dy + dz * dz + dw * dw;
    #pragma unroll
    for (int o = 16; o > 0; o >>= 1) s2 += __shfl_down_sync(0xffffffffu, s2, o);
    if ((t & 31) == 0) red[t >> 5] = s2;
    __syncthreads();
    float var = (red[0] + red[1] + red[2] + red[3]) * (1.0f / EDIM);
    float rs = rsqrtf(var + 1e-5f);

    float4 gv = ((const float4*)g)[t];
    float4 bv = ((const float4*)b)[t];
    float4 o4;
    o4.x = dx * rs * gv.x + bv.x;
    o4.y = dy * rs * gv.y + bv.y;
    o4.z = dz * rs * gv.z + bv.z;
    o4.w = dw * rs * gv.w + bv.w;
    ((float4*)(Y + (size_t)row * EDIM))[t] = o4;
}

// ---------------------------------------------------------------------------
// SGEMM (FFMA2): C[M,N] = A[M,K]*B[N,K]^T + bias (+res) (+relu)
// 128x128x8 tile, 256 threads, 8x8 per thread (packed as 8x4 f32x2 pairs),
// double-buffered smem.
// ---------------------------------------------------------------------------
template <bool RELU, bool RES>
__global__ void __launch_bounds__(256, 2)
sgemm_kernel(const float* __restrict__ A, const float* __restrict__ B,
             const float* __restrict__ bias, const float* __restrict__ Rs,
             float* __restrict__ C, int M, int N, int K) {
    __shared__ float As[2][8][128];
    __shared__ float Bs[2][8][128];

    const int t = threadIdx.x;
    const int mBase = blockIdx.y * 128;
    const int nBase = blockIdx.x * 128;

    const int lr = t >> 1;
    const int lc = (t & 1) * 4;
    const float* Aptr = A + (size_t)(mBase + lr) * K + lc;
    const float* Bptr = B + (size_t)(nBase + lr) * K + lc;

    const int tr = (t >> 4) * 8;
    const int tc = (t & 15) * 8;

    u64 acc[8][4];
    const u64 z = pack2(0.0f);
    #pragma unroll
    for (int i = 0; i < 8; i++)
        #pragma unroll
        for (int j = 0; j < 4; j++) acc[i][j] = z;

    // preload tile 0
    {
        float4 a4 = *(const float4*)(Aptr);
        float4 b4 = *(const float4*)(Bptr);
        As[0][lc + 0][lr] = a4.x; As[0][lc + 1][lr] = a4.y;
        As[0][lc + 2][lr] = a4.z; As[0][lc + 3][lr] = a4.w;
        Bs[0][lc + 0][lr] = b4.x; Bs[0][lc + 1][lr] = b4.y;
        Bs[0][lc + 2][lr] = b4.z; Bs[0][lc + 3][lr] = b4.w;
    }
    __syncthreads();

    const int T = K >> 3;
    for (int tile = 0; tile < T; tile++) {
        const int cur = tile & 1;
        const int nxt = cur ^ 1;
        float4 na, nb;
        const bool more = (tile + 1 < T);
        if (more) {
            na = *(const float4*)(Aptr + (size_t)(tile + 1) * 8);
            nb = *(const float4*)(Bptr + (size_t)(tile + 1) * 8);
        }

        #pragma unroll
        for (int kk = 0; kk < 8; kk++) {
            float4 ra0 = *(const float4*)&As[cur][kk][tr];
            float4 ra1 = *(const float4*)&As[cur][kk][tr + 4];
            ulonglong2 rb0 = *(const ulonglong2*)&Bs[cur][kk][tc];
            ulonglong2 rb1 = *(const ulonglong2*)&Bs[cur][kk][tc + 4];
            u64 rb[4] = {rb0.x, rb0.y, rb1.x, rb1.y};
            u64 pa[8];
            pa[0] = pack2(ra0.x); pa[1] = pack2(ra0.y);
            pa[2] = pack2(ra0.z); pa[3] = pack2(ra0.w);
            pa[4] = pack2(ra1.x); pa[5] = pack2(ra1.y);
            pa[6] = pack2(ra1.z); pa[7] = pack2(ra1.w);
            #pragma unroll
            for (int i = 0; i < 8; i++)
                #pragma unroll
                for (int j = 0; j < 4; j++)
                    acc[i][j] = fma2(pa[i], rb[j], acc[i][j]);
        }

        if (more) {
            As[nxt][lc + 0][lr] = na.x; As[nxt][lc + 1][lr] = na.y;
            As[nxt][lc + 2][lr] = na.z; As[nxt][lc + 3][lr] = na.w;
            Bs[nxt][lc + 0][lr] = nb.x; Bs[nxt][lc + 1][lr] = nb.y;
            Bs[nxt][lc + 2][lr] = nb.z; Bs[nxt][lc + 3][lr] = nb.w;
        }
        __syncthreads();
    }

    // Epilogue
    #pragma unroll
    for (int i = 0; i < 8; i++) {
        const int row = mBase + tr + i;
        float* crow = C + (size_t)row * N + nBase + tc;
        const float* rrow = RES ? (Rs + (size_t)row * N + nBase + tc) : nullptr;
        float vals[8];
        #pragma unroll
        for (int j = 0; j < 4; j++) {
            float2 p = unpack2(acc[i][j]);
            vals[2 * j] = p.x; vals[2 * j + 1] = p.y;
        }
        #pragma unroll
        for (int j4 = 0; j4 < 8; j4 += 4) {
            float4 o;
            float* op = &o.x;
            #pragma unroll
            for (int j = 0; j < 4; j++) {
                float c = vals[j4 + j] + bias[nBase + tc + j4 + j];
                if (RES) c += rrow[j4 + j];
                if (RELU) c = fmaxf(c, 0.0f);
                op[j] = c;
            }
            *(float4*)(crow + j4) = o;
        }
    }
}

// ---------------------------------------------------------------------------
// Flash attention (FFMA2): one block per (head, 64-query block). 256 threads.
// qkv layout per token row (1536): [s(3)][h(8)][d(64)]
// K stored TRANSPOSED in smem so QK^T pairs along key index are contiguous.
// Strides padded to 68 floats (16B-aligned rows for LDS.128).
// ---------------------------------------------------------------------------
#define QS_STRIDE 68
#define KT_STRIDE 68
#define SS_STRIDE 68

__global__ void __launch_bounds__(256, 2)
attn_kernel(const float* __restrict__ qkv, float* __restrict__ out) {
    extern __shared__ float sm[];
    float* Qs  = sm;                      // 64 x 68  (Qs[r*68+d])
    float* KsT = Qs + 64 * QS_STRIDE;     // 64 x 68  (KsT[d*68+r])
    float* Ss  = KsT + 64 * KT_STRIDE;    // 64 x 68  (Ss[r*68+c])
    float* Vs  = Ss + 64 * SS_STRIDE;     // 64 x 64  (Vs[k*64+c])
    float* rowM = Vs + 64 * 64;
    float* rowL = rowM + 64;
    float* rowA = rowL + 64;

    const int t = threadIdx.x;            // 256
    const int h = blockIdx.y;
    const int qb = blockIdx.x * 64;
    const float scale = 0.125f;           // 1/sqrt(64)

    // Load Q tile (scaled)
    for (int idx = t; idx < 64 * 64; idx += 256) {
        int r = idx >> 6, d = idx & 63;
        Qs[r * QS_STRIDE + d] = qkv[(size_t)(qb + r) * 1536 + h * 64 + d] * scale;
    }
    if (t < 64) { rowM[t] = -1e30f; rowL[t] = 0.0f; }

    const int ty = t >> 4, tx = t & 15;
    const int r0 = ty * 4, c0 = tx * 4;
    u64 acc2[4][2];
    const u64 z = pack2(0.0f);
    #pragma unroll
    for (int i = 0; i < 4; i++) { acc2[i][0] = z; acc2[i][1] = z; }

    for (int kb = 0; kb < NSEQ; kb += 64) {
        __syncthreads();  // prev iter done with KsT/Vs/Ss (also covers Q load)
        for (int idx = t; idx < 64 * 64; idx += 256) {
            int r = idx >> 6, d = idx & 63;
            const float* base = qkv + (size_t)(kb + r) * 1536 + h * 64 + d;
            KsT[d * KT_STRIDE + r] = base[512];
            Vs[idx]                = base[1024];
        }
        __syncthreads();

        // S = Q * K^T  (packed along key index pairs)
        u64 s2[4][2];
        #pragma unroll
        for (int i = 0; i < 4; i++) { s2[i][0] = z; s2[i][1] = z; }

        #pragma unroll 2
        for (int d0 = 0; d0 < 64; d0 += 4) {
            float qa[4][4];
            #pragma unroll
            for (int i = 0; i < 4; i++) {
                float4 q4 = *(const float4*)&Qs[(r0 + i) * QS_STRIDE + d0];
                qa[i][0] = q4.x; qa[i][1] = q4.y; qa[i][2] = q4.z; qa[i][3] = q4.w;
            }
            #pragma unroll
            for (int dd = 0; dd < 4; dd++) {
                ulonglong2 kbp = *(const ulonglong2*)&KsT[(d0 + dd) * KT_STRIDE + c0];
                #pragma unroll
                for (int i = 0; i < 4; i++) {
                    u64 pq = pack2(qa[i][dd]);
                    s2[i][0] = fma2(pq, kbp.x, s2[i][0]);
                    s2[i][1] = fma2(pq, kbp.y, s2[i][1]);
                }
            }
        }
        #pragma unroll
        for (int i = 0; i < 4; i++) {
            float2 p0 = unpack2(s2[i][0]);
            float2 p1 = unpack2(s2[i][1]);
            float* sr = &Ss[(r0 + i) * SS_STRIDE + c0];
            sr[0] = p0.x; sr[1] = p0.y; sr[2] = p1.x; sr[3] = p1.y;
        }
        __syncthreads();

        // Online softmax (64 threads, one per row)
        if (t < 64) {
            float* Sr = Ss + t * SS_STRIDE;
            float mx = rowM[t];
            #pragma unroll 8
            for (int j = 0; j < 64; j++) mx = fmaxf(mx, Sr[j]);
            float al = __expf(rowM[t] - mx);
            float sum = 0.0f;
            #pragma unroll 8
            for (int j = 0; j < 64; j++) {
                float p = __expf(Sr[j] - mx);
                Sr[j] = p;
                sum += p;
            }
            rowL[t] = rowL[t] * al + sum;
            rowM[t] = mx;
            rowA[t] = al;
        }
        __syncthreads();

        // O = O*alpha + P*V (packed along V columns)
        #pragma unroll
        for (int i = 0; i < 4; i++) {
            u64 pal = pack2(rowA[r0 + i]);
            acc2[i][0] = mul2(acc2[i][0], pal);
            acc2[i][1] = mul2(acc2[i][1], pal);
        }
        #pragma unroll 2
        for (int k0 = 0; k0 < 64; k0 += 4) {
            float pa_[4][4];
            #pragma unroll
            for (int i = 0; i < 4; i++) {
                float4 p4 = *(const float4*)&Ss[(r0 + i) * SS_STRIDE + k0];
                pa_[i][0] = p4.x; pa_[i][1] = p4.y; pa_[i][2] = p4.z; pa_[i][3] = p4.w;
            }
            #pragma unroll
            for (int kk = 0; kk < 4; kk++) {
                ulonglong2 vv = *(const ulonglong2*)&Vs[(k0 + kk) * 64 + c0];
                #pragma unroll
                for (int i = 0; i < 4; i++) {
                    u64 pp = pack2(pa_[i][kk]);
                    acc2[i][0] = fma2(pp, vv.x, acc2[i][0]);
                    acc2[i][1] = fma2(pp, vv.y, acc2[i][1]);
                }
            }
        }
    }
    __syncthreads();

    // Normalize + store
    #pragma unroll
    for (int i = 0; i < 4; i++) {
        float inv = 1.0f / rowL[r0 + i];
        float2 p0 = unpack2(acc2[i][0]);
        float2 p1 = unpack2(acc2[i][1]);
        float* orow = out + (size_t)(qb + r0 + i) * EDIM + h * 64 + c0;
        orow[0] = p0.x * inv; orow[1] = p0.y * inv;
        orow[2] = p1.x * inv; orow[3] = p1.y * inv;
    }
}

static const int ATTN_SMEM = (3 * 64 * 68 + 64 * 64 + 3 * 64) * sizeof(float);  // 69,376 B

extern "C" void kernel_launch(void* const* d_in, const int* in_sizes, int n_in,
                              void* d_out, int out_size) {
    const float* x      = (const float*)d_in[0];
    const float* ln_g   = (const float*)d_in[1];
    const float* ln_b   = (const float*)d_in[2];
    const float* qkv_w  = (const float*)d_in[3];
    const float* qkv_b  = (const float*)d_in[4];
    const float* proj_w = (const float*)d_in[5];
    const float* proj_b = (const float*)d_in[6];
    const float* fc1_w  = (const float*)d_in[7];
    const float* fc1_b  = (const float*)d_in[8];
    const float* fc2_w  = (const float*)d_in[9];
    const float* fc2_b  = (const float*)d_in[10];
    const float* fc3_w  = (const float*)d_in[11];
    const float* fc3_b  = (const float*)d_in[12];
    float* out = (float*)d_out;

    float *h1, *qkvb, *attnb, *x1, *h2, *m1, *m2;
    cudaGetSymbolAddress((void**)&h1, g_h1);
    cudaGetSymbolAddress((void**)&qkvb, g_qkv);
    cudaGetSymbolAddress((void**)&attnb, g_attn);
    cudaGetSymbolAddress((void**)&x1, g_x1);
    cudaGetSymbolAddress((void**)&h2, g_h2);
    cudaGetSymbolAddress((void**)&m1, g_m1);
    cudaGetSymbolAddress((void**)&m2, g_m2);

    cudaFuncSetAttribute(attn_kernel, cudaFuncAttributeMaxDynamicSharedMemorySize, ATTN_SMEM);

    // 1. LN1
    ln_kernel<<<NSEQ, 128>>>(x, ln_g, ln_b, h1);
    // 2. QKV
    sgemm_kernel<false, false><<<dim3(12, 32), 256>>>(h1, qkv_w, qkv_b, nullptr, qkvb,
                                                      NSEQ, 3 * EDIM, EDIM);
    // 3. Attention
    attn_kernel<<<dim3(64, NHEAD), 256, ATTN_SMEM>>>(qkvb, attnb);
    // 4. proj + residual
    sgemm_kernel<false, true><<<dim3(4, 32), 256>>>(attnb, proj_w, proj_b, x, x1,
                                                    NSEQ, EDIM, EDIM);
    // 5. LN2
    ln_kernel<<<NSEQ, 128>>>(x1, ln_g, ln_b, h2);
    // 6. fc1 + relu
    sgemm_kernel<true, false><<<dim3(16, 32), 256>>>(h2, fc1_w, fc1_b, nullptr, m1,
                                                     NSEQ, HDIM, EDIM);
    // 7. fc2 + relu
    sgemm_kernel<true, false><<<dim3(16, 32), 256>>>(m1, fc2_w, fc2_b, nullptr, m2,
                                                     NSEQ, HDIM, HDIM);
    // 8. fc3 + bias + residual -> out
    sgemm_kernel<false, true><<<dim3(4, 32), 256>>>(m2, fc3_w, fc3_b, x1, out,
                                                    NSEQ, EDIM, HDIM);
}

// round 6
// speedup vs baseline: 1.6229x; 1.4637x over previous
#include <cuda_runtime.h>
#include <cstdint>
#include <math.h>

// Problem constants
#define EDIM 512
#define NSEQ 4096
#define NHEAD 8
#define HDIM 2048

typedef unsigned long long u64;

// ---- packed f32x2 helpers (FFMA2 path for attention) ----
__device__ __forceinline__ u64 pack2(float v) {
    u64 r; unsigned u = __float_as_uint(v);
    asm("mov.b64 %0, {%1, %1};" : "=l"(r) : "r"(u));
    return r;
}
__device__ __forceinline__ u64 fma2(u64 a, u64 b, u64 c) {
    u64 d;
    asm("fma.rn.f32x2 %0, %1, %2, %3;" : "=l"(d) : "l"(a), "l"(b), "l"(c));
    return d;
}
__device__ __forceinline__ u64 mul2(u64 a, u64 b) {
    u64 d;
    asm("mul.rn.f32x2 %0, %1, %2;" : "=l"(d) : "l"(a), "l"(b), "l"(b));
    return d;
}
__device__ __forceinline__ float2 unpack2(u64 v) {
    unsigned lo, hi;
    asm("mov.b64 {%0, %1}, %2;" : "=r"(lo), "=r"(hi) : "l"(v));
    float2 f; f.x = __uint_as_float(lo); f.y = __uint_as_float(hi);
    return f;
}

// ---- tf32 mma.sync helpers (family-agnostic PTX, works on compute_103) ----
__device__ __forceinline__ uint32_t tf32r(float f) {
    uint32_t u;
    asm("cvt.rna.tf32.f32 %0, %1;" : "=r"(u) : "f"(f));
    return u;
}
__device__ __forceinline__ void mma1688(float* c, const uint32_t* a, const uint32_t* b) {
    asm volatile(
        "mma.sync.aligned.m16n8k8.row.col.f32.tf32.tf32.f32 "
        "{%0,%1,%2,%3}, {%4,%5,%6,%7}, {%8,%9}, {%0,%1,%2,%3};"
        : "+f"(c[0]), "+f"(c[1]), "+f"(c[2]), "+f"(c[3])
        : "r"(a[0]), "r"(a[1]), "r"(a[2]), "r"(a[3]), "r"(b[0]), "r"(b[1]));
}

// Scratch (alloc-free rule: __device__ globals)
__device__ float g_h1[NSEQ * EDIM];
__device__ float g_qkv[NSEQ * 3 * EDIM];
__device__ float g_attn[NSEQ * EDIM];
__device__ float g_x1[NSEQ * EDIM];
__device__ float g_h2[NSEQ * EDIM];
__device__ float g_m1[NSEQ * HDIM];
__device__ float g_m2[NSEQ * HDIM];

// ===========================================================================
// LayerNorm
// ===========================================================================
__global__ void ln_kernel(const float* __restrict__ X, const float* __restrict__ g,
                          const float* __restrict__ b, float* __restrict__ Y) {
    const int row = blockIdx.x;
    const int t = threadIdx.x;  // 128 threads
    const float4* Xv = (const float4*)(X + (size_t)row * EDIM);
    float4 v = Xv[t];

    __shared__ float red[4];
    float s = v.x + v.y + v.z + v.w;
    #pragma unroll
    for (int o = 16; o > 0; o >>= 1) s += __shfl_down_sync(0xffffffffu, s, o);
    if ((t & 31) == 0) red[t >> 5] = s;
    __syncthreads();
    float mean = (red[0] + red[1] + red[2] + red[3]) * (1.0f / EDIM);
    __syncthreads();

    float dx = v.x - mean, dy = v.y - mean, dz = v.z - mean, dw = v.w - mean;
    float s2 = dx * dx + dy * dy + dz * dz + dw * dw;
    #pragma unroll
    for (int o = 16; o > 0; o >>= 1) s2 += __shfl_down_sync(0xffffffffu, s2, o);
    if ((t & 31) == 0) red[t >> 5] = s2;
    __syncthreads();
    float var = (red[0] + red[1] + red[2] + red[3]) * (1.0f / EDIM);
    float rs = rsqrtf(var + 1e-5f);

    float4 gv = ((const float4*)g)[t];
    float4 bv = ((const float4*)b)[t];
    float4 o4;
    o4.x = dx * rs * gv.x + bv.x;
    o4.y = dy * rs * gv.y + bv.y;
    o4.z = dz * rs * gv.z + bv.z;
    o4.w = dw * rs * gv.w + bv.w;
    ((float4*)(Y + (size_t)row * EDIM))[t] = o4;
}

// ===========================================================================
// tf32 mma.sync GEMM: C[M,N] = A[M,K]*B[N,K]^T (+bias, +res, +relu)
// CTA 128x128, 8 warps (2x4), warp tile 64x32, K-chunk 16, double-buffered.
// smem row stride = 20 floats (conflict-free fragment access, 16B aligned).
// ===========================================================================
#define SMS 20   // smem row stride (floats)

template <bool RELU, bool RES>
__global__ void __launch_bounds__(256)
mma_gemm(const float* __restrict__ A, const float* __restrict__ B,
         const float* __restrict__ bias, const float* __restrict__ Rs,
         float* __restrict__ C, int M, int N, int K) {
    __shared__ uint32_t sA[2][128 * SMS];
    __shared__ uint32_t sB[2][128 * SMS];

    const int t = threadIdx.x;
    const int wid = t >> 5;
    const int lid = t & 31;
    const int mBase = blockIdx.y * 128;
    const int nBase = blockIdx.x * 128;

    const int wm = (wid >> 2) * 64;   // warp row offset
    const int wn = (wid & 3) * 32;    // warp col offset
    const int g = lid >> 2;           // group id (0..7)
    const int t4 = lid & 3;           // thread in group (0..3)

    float acc[4][4][4];
    #pragma unroll
    for (int mi = 0; mi < 4; mi++)
        #pragma unroll
        for (int ni = 0; ni < 4; ni++)
            #pragma unroll
            for (int r = 0; r < 4; r++) acc[mi][ni][r] = 0.0f;

    // loader indexing: 512 float4 slots per tile (128 rows x 4), 2 per thread
    const int s0 = t * 2;
    const int lrow0 = s0 >> 2, lq0 = (s0 & 3) * 4;
    const int lrow1 = (s0 + 1) >> 2, lq1 = ((s0 + 1) & 3) * 4;

    auto load_chunk = [&](int k0, int buf) {
        float4 a0 = *(const float4*)(A + (size_t)(mBase + lrow0) * K + k0 + lq0);
        float4 a1 = *(const float4*)(A + (size_t)(mBase + lrow1) * K + k0 + lq1);
        float4 b0 = *(const float4*)(B + (size_t)(nBase + lrow0) * K + k0 + lq0);
        float4 b1 = *(const float4*)(B + (size_t)(nBase + lrow1) * K + k0 + lq1);
        uint4 ua0 = {tf32r(a0.x), tf32r(a0.y), tf32r(a0.z), tf32r(a0.w)};
        uint4 ua1 = {tf32r(a1.x), tf32r(a1.y), tf32r(a1.z), tf32r(a1.w)};
        uint4 ub0 = {tf32r(b0.x), tf32r(b0.y), tf32r(b0.z), tf32r(b0.w)};
        uint4 ub1 = {tf32r(b1.x), tf32r(b1.y), tf32r(b1.z), tf32r(b1.w)};
        *(uint4*)&sA[buf][lrow0 * SMS + lq0] = ua0;
        *(uint4*)&sA[buf][lrow1 * SMS + lq1] = ua1;
        *(uint4*)&sB[buf][lrow0 * SMS + lq0] = ub0;
        *(uint4*)&sB[buf][lrow1 * SMS + lq1] = ub1;
    };

    load_chunk(0, 0);
    __syncthreads();

    const int T = K >> 4;  // chunks of 16
    for (int c = 0; c < T; c++) {
        const int cur = c & 1;
        // prefetch next chunk into registers
        float4 na0, na1, nb0, nb1;
        const bool more = (c + 1 < T);
        if (more) {
            const int k0 = (c + 1) << 4;
            na0 = *(const float4*)(A + (size_t)(mBase + lrow0) * K + k0 + lq0);
            na1 = *(const float4*)(A + (size_t)(mBase + lrow1) * K + k0 + lq1);
            nb0 = *(const float4*)(B + (size_t)(nBase + lrow0) * K + k0 + lq0);
            nb1 = *(const float4*)(B + (size_t)(nBase + lrow1) * K + k0 + lq1);
        }

        // compute on current buffer: 2 k8 steps
        #pragma unroll
        for (int ks = 0; ks < 16; ks += 8) {
            uint32_t af[4][4], bf[4][2];
            #pragma unroll
            for (int mi = 0; mi < 4; mi++) {
                int base = (wm + mi * 16 + g) * SMS + ks + t4;
                af[mi][0] = sA[cur][base];
                af[mi][1] = sA[cur][base + 8 * SMS];
                af[mi][2] = sA[cur][base + 4];
                af[mi][3] = sA[cur][base + 8 * SMS + 4];
            }
            #pragma unroll
            for (int ni = 0; ni < 4; ni++) {
                int base = (wn + ni * 8 + g) * SMS + ks + t4;
                bf[ni][0] = sB[cur][base];
                bf[ni][1] = sB[cur][base + 4];
            }
            #pragma unroll
            for (int mi = 0; mi < 4; mi++)
                #pragma unroll
                for (int ni = 0; ni < 4; ni++)
                    mma1688(acc[mi][ni], af[mi], bf[ni]);
        }

        if (more) {
            const int nxt = cur ^ 1;
            uint4 ua0 = {tf32r(na0.x), tf32r(na0.y), tf32r(na0.z), tf32r(na0.w)};
            uint4 ua1 = {tf32r(na1.x), tf32r(na1.y), tf32r(na1.z), tf32r(na1.w)};
            uint4 ub0 = {tf32r(nb0.x), tf32r(nb0.y), tf32r(nb0.z), tf32r(nb0.w)};
            uint4 ub1 = {tf32r(nb1.x), tf32r(nb1.y), tf32r(nb1.z), tf32r(nb1.w)};
            *(uint4*)&sA[nxt][lrow0 * SMS + lq0] = ua0;
            *(uint4*)&sA[nxt][lrow1 * SMS + lq1] = ua1;
            *(uint4*)&sB[nxt][lrow0 * SMS + lq0] = ub0;
            *(uint4*)&sB[nxt][lrow1 * SMS + lq1] = ub1;
        }
        __syncthreads();
    }

    // Epilogue: acc[mi][ni] rows {wm+mi*16+g, +8}, cols {wn+ni*8+2*t4, +1}
    #pragma unroll
    for (int mi = 0; mi < 4; mi++) {
        #pragma unroll
        for (int ni = 0; ni < 4; ni++) {
            const int cc = nBase + wn + ni * 8 + 2 * t4;
            const float b0 = bias[cc], b1 = bias[cc + 1];
            #pragma unroll
            for (int h = 0; h < 2; h++) {
                const int row = mBase + wm + mi * 16 + g + h * 8;
                float v0 = acc[mi][ni][2 * h + 0] + b0;
                float v1 = acc[mi][ni][2 * h + 1] + b1;
                if (RES) {
                    const float* rr = Rs + (size_t)row * N + cc;
                    v0 += rr[0]; v1 += rr[1];
                }
                if (RELU) { v0 = fmaxf(v0, 0.0f); v1 = fmaxf(v1, 0.0f); }
                float2 o; o.x = v0; o.y = v1;
                *(float2*)(C + (size_t)row * N + cc) = o;
            }
        }
    }
}

// ===========================================================================
// Flash attention (FFMA2) — unchanged from R2 (passing)
// ===========================================================================
#define QS_STRIDE 68
#define KT_STRIDE 68
#define SS_STRIDE 68

__global__ void __launch_bounds__(256, 2)
attn_kernel(const float* __restrict__ qkv, float* __restrict__ out) {
    extern __shared__ float sm[];
    float* Qs  = sm;
    float* KsT = Qs + 64 * QS_STRIDE;
    float* Ss  = KsT + 64 * KT_STRIDE;
    float* Vs  = Ss + 64 * SS_STRIDE;
    float* rowM = Vs + 64 * 64;
    float* rowL = rowM + 64;
    float* rowA = rowL + 64;

    const int t = threadIdx.x;
    const int h = blockIdx.y;
    const int qb = blockIdx.x * 64;
    const float scale = 0.125f;

    for (int idx = t; idx < 64 * 64; idx += 256) {
        int r = idx >> 6, d = idx & 63;
        Qs[r * QS_STRIDE + d] = qkv[(size_t)(qb + r) * 1536 + h * 64 + d] * scale;
    }
    if (t < 64) { rowM[t] = -1e30f; rowL[t] = 0.0f; }

    const int ty = t >> 4, tx = t & 15;
    const int r0 = ty * 4, c0 = tx * 4;
    u64 acc2[4][2];
    const u64 z = pack2(0.0f);
    #pragma unroll
    for (int i = 0; i < 4; i++) { acc2[i][0] = z; acc2[i][1] = z; }

    for (int kb = 0; kb < NSEQ; kb += 64) {
        __syncthreads();
        for (int idx = t; idx < 64 * 64; idx += 256) {
            int r = idx >> 6, d = idx & 63;
            const float* base = qkv + (size_t)(kb + r) * 1536 + h * 64 + d;
            KsT[d * KT_STRIDE + r] = base[512];
            Vs[idx]                = base[1024];
        }
        __syncthreads();

        u64 s2[4][2];
        #pragma unroll
        for (int i = 0; i < 4; i++) { s2[i][0] = z; s2[i][1] = z; }

        #pragma unroll 2
        for (int d0 = 0; d0 < 64; d0 += 4) {
            float qa[4][4];
            #pragma unroll
            for (int i = 0; i < 4; i++) {
                float4 q4 = *(const float4*)&Qs[(r0 + i) * QS_STRIDE + d0];
                qa[i][0] = q4.x; qa[i][1] = q4.y; qa[i][2] = q4.z; qa[i][3] = q4.w;
            }
            #pragma unroll
            for (int dd = 0; dd < 4; dd++) {
                ulonglong2 kbp = *(const ulonglong2*)&KsT[(d0 + dd) * KT_STRIDE + c0];
                #pragma unroll
                for (int i = 0; i < 4; i++) {
                    u64 pq = pack2(qa[i][dd]);
                    s2[i][0] = fma2(pq, kbp.x, s2[i][0]);
                    s2[i][1] = fma2(pq, kbp.y, s2[i][1]);
                }
            }
        }
        #pragma unroll
        for (int i = 0; i < 4; i++) {
            float2 p0 = unpack2(s2[i][0]);
            float2 p1 = unpack2(s2[i][1]);
            float* sr = &Ss[(r0 + i) * SS_STRIDE + c0];
            sr[0] = p0.x; sr[1] = p0.y; sr[2] = p1.x; sr[3] = p1.y;
        }
        __syncthreads();

        if (t < 64) {
            float* Sr = Ss + t * SS_STRIDE;
            float mx = rowM[t];
            #pragma unroll 8
            for (int j = 0; j < 64; j++) mx = fmaxf(mx, Sr[j]);
            float al = __expf(rowM[t] - mx);
            float sum = 0.0f;
            #pragma unroll 8
            for (int j = 0; j < 64; j++) {
                float p = __expf(Sr[j] - mx);
                Sr[j] = p;
                sum += p;
            }
            rowL[t] = rowL[t] * al + sum;
            rowM[t] = mx;
            rowA[t] = al;
        }
        __syncthreads();

        #pragma unroll
        for (int i = 0; i < 4; i++) {
            u64 pal = pack2(rowA[r0 + i]);
            // acc *= alpha  (use fma2 with zero addend to avoid mul2 helper quirk)
            acc2[i][0] = fma2(acc2[i][0], pal, z);
            acc2[i][1] = fma2(acc2[i][1], pal, z);
        }
        #pragma unroll 2
        for (int k0 = 0; k0 < 64; k0 += 4) {
            float pa_[4][4];
            #pragma unroll
            for (int i = 0; i < 4; i++) {
                float4 p4 = *(const float4*)&Ss[(r0 + i) * SS_STRIDE + k0];
                pa_[i][0] = p4.x; pa_[i][1] = p4.y; pa_[i][2] = p4.z; pa_[i][3] = p4.w;
            }
            #pragma unroll
            for (int kk = 0; kk < 4; kk++) {
                ulonglong2 vv = *(const ulonglong2*)&Vs[(k0 + kk) * 64 + c0];
                #pragma unroll
                for (int i = 0; i < 4; i++) {
                    u64 pp = pack2(pa_[i][kk]);
                    acc2[i][0] = fma2(pp, vv.x, acc2[i][0]);
                    acc2[i][1] = fma2(pp, vv.y, acc2[i][1]);
                }
            }
        }
    }
    __syncthreads();

    #pragma unroll
    for (int i = 0; i < 4; i++) {
        float inv = 1.0f / rowL[r0 + i];
        float2 p0 = unpack2(acc2[i][0]);
        float2 p1 = unpack2(acc2[i][1]);
        float* orow = out + (size_t)(qb + r0 + i) * EDIM + h * 64 + c0;
        orow[0] = p0.x * inv; orow[1] = p0.y * inv;
        orow[2] = p1.x * inv; orow[3] = p1.y * inv;
    }
}

static const int ATTN_SMEM = (3 * 64 * 68 + 64 * 64 + 3 * 64) * sizeof(float);

extern "C" void kernel_launch(void* const* d_in, const int* in_sizes, int n_in,
                              void* d_out, int out_size) {
    const float* x      = (const float*)d_in[0];
    const float* ln_g   = (const float*)d_in[1];
    const float* ln_b   = (const float*)d_in[2];
    const float* qkv_w  = (const float*)d_in[3];
    const float* qkv_b  = (const float*)d_in[4];
    const float* proj_w = (const float*)d_in[5];
    const float* proj_b = (const float*)d_in[6];
    const float* fc1_w  = (const float*)d_in[7];
    const float* fc1_b  = (const float*)d_in[8];
    const float* fc2_w  = (const float*)d_in[9];
    const float* fc2_b  = (const float*)d_in[10];
    const float* fc3_w  = (const float*)d_in[11];
    const float* fc3_b  = (const float*)d_in[12];
    float* out = (float*)d_out;

    float *h1, *qkvb, *attnb, *x1, *h2, *m1, *m2;
    cudaGetSymbolAddress((void**)&h1, g_h1);
    cudaGetSymbolAddress((void**)&qkvb, g_qkv);
    cudaGetSymbolAddress((void**)&attnb, g_attn);
    cudaGetSymbolAddress((void**)&x1, g_x1);
    cudaGetSymbolAddress((void**)&h2, g_h2);
    cudaGetSymbolAddress((void**)&m1, g_m1);
    cudaGetSymbolAddress((void**)&m2, g_m2);

    cudaFuncSetAttribute(attn_kernel, cudaFuncAttributeMaxDynamicSharedMemorySize, ATTN_SMEM);

    // 1. LN1
    ln_kernel<<<NSEQ, 128>>>(x, ln_g, ln_b, h1);
    // 2. QKV: [4096,512] x [1536,512]^T
    mma_gemm<false, false><<<dim3(12, 32), 256>>>(h1, qkv_w, qkv_b, nullptr, qkvb,
                                                  NSEQ, 3 * EDIM, EDIM);
    // 3. Attention
    attn_kernel<<<dim3(64, NHEAD), 256, ATTN_SMEM>>>(qkvb, attnb);
    // 4. proj + residual
    mma_gemm<false, true><<<dim3(4, 32), 256>>>(attnb, proj_w, proj_b, x, x1,
                                                NSEQ, EDIM, EDIM);
    // 5. LN2
    ln_kernel<<<NSEQ, 128>>>(x1, ln_g, ln_b, h2);
    // 6. fc1 + relu
    mma_gemm<true, false><<<dim3(16, 32), 256>>>(h2, fc1_w, fc1_b, nullptr, m1,
                                                 NSEQ, HDIM, EDIM);
    // 7. fc2 + relu
    mma_gemm<true, false><<<dim3(16, 32), 256>>>(m1, fc2_w, fc2_b, nullptr, m2,
                                                 NSEQ, HDIM, HDIM);
    // 8. fc3 + bias + residual -> out
    mma_gemm<false, true><<<dim3(4, 32), 256>>>(m2, fc3_w, fc3_b, x1, out,
                                                NSEQ, EDIM, HDIM);
}

// round 7
// speedup vs baseline: 2.4849x; 1.5311x over previous
#include <cuda_runtime.h>
#include <cstdint>
#include <math.h>

// Problem constants
#define EDIM 512
#define NSEQ 4096
#define NHEAD 8
#define HDIM 2048

typedef unsigned long long u64;

// ---- tf32 mma.sync helpers (family-agnostic PTX, works on compute_103) ----
__device__ __forceinline__ uint32_t tf32r(float f) {
    uint32_t u;
    asm("cvt.rna.tf32.f32 %0, %1;" : "=r"(u) : "f"(f));
    return u;
}
__device__ __forceinline__ void mma1688(float* c, const uint32_t* a, const uint32_t* b) {
    asm volatile(
        "mma.sync.aligned.m16n8k8.row.col.f32.tf32.tf32.f32 "
        "{%0,%1,%2,%3}, {%4,%5,%6,%7}, {%8,%9}, {%0,%1,%2,%3};"
        : "+f"(c[0]), "+f"(c[1]), "+f"(c[2]), "+f"(c[3])
        : "r"(a[0]), "r"(a[1]), "r"(a[2]), "r"(a[3]), "r"(b[0]), "r"(b[1]));
}

// Scratch (alloc-free rule: __device__ globals)
__device__ float g_h1[NSEQ * EDIM];
__device__ float g_qkv[NSEQ * 3 * EDIM];
__device__ float g_attn[NSEQ * EDIM];
__device__ float g_x1[NSEQ * EDIM];
__device__ float g_h2[NSEQ * EDIM];
__device__ float g_m1[NSEQ * HDIM];
__device__ float g_m2[NSEQ * HDIM];

// ===========================================================================
// LayerNorm
// ===========================================================================
__global__ void ln_kernel(const float* __restrict__ X, const float* __restrict__ g,
                          const float* __restrict__ b, float* __restrict__ Y) {
    const int row = blockIdx.x;
    const int t = threadIdx.x;  // 128 threads
    const float4* Xv = (const float4*)(X + (size_t)row * EDIM);
    float4 v = Xv[t];

    __shared__ float red[4];
    float s = v.x + v.y + v.z + v.w;
    #pragma unroll
    for (int o = 16; o > 0; o >>= 1) s += __shfl_down_sync(0xffffffffu, s, o);
    if ((t & 31) == 0) red[t >> 5] = s;
    __syncthreads();
    float mean = (red[0] + red[1] + red[2] + red[3]) * (1.0f / EDIM);
    __syncthreads();

    float dx = v.x - mean, dy = v.y - mean, dz = v.z - mean, dw = v.w - mean;
    float s2 = dx * dx + dy * dy + dz * dz + dw * dw;
    #pragma unroll
    for (int o = 16; o > 0; o >>= 1) s2 += __shfl_down_sync(0xffffffffu, s2, o);
    if ((t & 31) == 0) red[t >> 5] = s2;
    __syncthreads();
    float var = (red[0] + red[1] + red[2] + red[3]) * (1.0f / EDIM);
    float rs = rsqrtf(var + 1e-5f);

    float4 gv = ((const float4*)g)[t];
    float4 bv = ((const float4*)b)[t];
    float4 o4;
    o4.x = dx * rs * gv.x + bv.x;
    o4.y = dy * rs * gv.y + bv.y;
    o4.z = dz * rs * gv.z + bv.z;
    o4.w = dw * rs * gv.w + bv.w;
    ((float4*)(Y + (size_t)row * EDIM))[t] = o4;
}

// ===========================================================================
// tf32 mma.sync GEMM: C[M,N] = A[M,K]*B[N,K]^T (+bias, +res, +relu)
// CTA 128x128, 8 warps (2x4), warp tile 64x32, K-chunk 16, double-buffered.
// ===========================================================================
#define SMS 20   // smem row stride (floats)

template <bool RELU, bool RES>
__global__ void __launch_bounds__(256)
mma_gemm(const float* __restrict__ A, const float* __restrict__ B,
         const float* __restrict__ bias, const float* __restrict__ Rs,
         float* __restrict__ C, int M, int N, int K) {
    __shared__ uint32_t sA[2][128 * SMS];
    __shared__ uint32_t sB[2][128 * SMS];

    const int t = threadIdx.x;
    const int wid = t >> 5;
    const int lid = t & 31;
    const int mBase = blockIdx.y * 128;
    const int nBase = blockIdx.x * 128;

    const int wm = (wid >> 2) * 64;   // warp row offset
    const int wn = (wid & 3) * 32;    // warp col offset
    const int g = lid >> 2;           // group id (0..7)
    const int t4 = lid & 3;           // thread in group (0..3)

    float acc[4][4][4];
    #pragma unroll
    for (int mi = 0; mi < 4; mi++)
        #pragma unroll
        for (int ni = 0; ni < 4; ni++)
            #pragma unroll
            for (int r = 0; r < 4; r++) acc[mi][ni][r] = 0.0f;

    const int s0 = t * 2;
    const int lrow0 = s0 >> 2, lq0 = (s0 & 3) * 4;
    const int lrow1 = (s0 + 1) >> 2, lq1 = ((s0 + 1) & 3) * 4;

    auto load_chunk = [&](int k0, int buf) {
        float4 a0 = *(const float4*)(A + (size_t)(mBase + lrow0) * K + k0 + lq0);
        float4 a1 = *(const float4*)(A + (size_t)(mBase + lrow1) * K + k0 + lq1);
        float4 b0 = *(const float4*)(B + (size_t)(nBase + lrow0) * K + k0 + lq0);
        float4 b1 = *(const float4*)(B + (size_t)(nBase + lrow1) * K + k0 + lq1);
        uint4 ua0 = {tf32r(a0.x), tf32r(a0.y), tf32r(a0.z), tf32r(a0.w)};
        uint4 ua1 = {tf32r(a1.x), tf32r(a1.y), tf32r(a1.z), tf32r(a1.w)};
        uint4 ub0 = {tf32r(b0.x), tf32r(b0.y), tf32r(b0.z), tf32r(b0.w)};
        uint4 ub1 = {tf32r(b1.x), tf32r(b1.y), tf32r(b1.z), tf32r(b1.w)};
        *(uint4*)&sA[buf][lrow0 * SMS + lq0] = ua0;
        *(uint4*)&sA[buf][lrow1 * SMS + lq1] = ua1;
        *(uint4*)&sB[buf][lrow0 * SMS + lq0] = ub0;
        *(uint4*)&sB[buf][lrow1 * SMS + lq1] = ub1;
    };

    load_chunk(0, 0);
    __syncthreads();

    const int T = K >> 4;
    for (int c = 0; c < T; c++) {
        const int cur = c & 1;
        float4 na0, na1, nb0, nb1;
        const bool more = (c + 1 < T);
        if (more) {
            const int k0 = (c + 1) << 4;
            na0 = *(const float4*)(A + (size_t)(mBase + lrow0) * K + k0 + lq0);
            na1 = *(const float4*)(A + (size_t)(mBase + lrow1) * K + k0 + lq1);
            nb0 = *(const float4*)(B + (size_t)(nBase + lrow0) * K + k0 + lq0);
            nb1 = *(const float4*)(B + (size_t)(nBase + lrow1) * K + k0 + lq1);
        }

        #pragma unroll
        for (int ks = 0; ks < 16; ks += 8) {
            uint32_t af[4][4], bf[4][2];
            #pragma unroll
            for (int mi = 0; mi < 4; mi++) {
                int base = (wm + mi * 16 + g) * SMS + ks + t4;
                af[mi][0] = sA[cur][base];
                af[mi][1] = sA[cur][base + 8 * SMS];
                af[mi][2] = sA[cur][base + 4];
                af[mi][3] = sA[cur][base + 8 * SMS + 4];
            }
            #pragma unroll
            for (int ni = 0; ni < 4; ni++) {
                int base = (wn + ni * 8 + g) * SMS + ks + t4;
                bf[ni][0] = sB[cur][base];
                bf[ni][1] = sB[cur][base + 4];
            }
            #pragma unroll
            for (int mi = 0; mi < 4; mi++)
                #pragma unroll
                for (int ni = 0; ni < 4; ni++)
                    mma1688(acc[mi][ni], af[mi], bf[ni]);
        }

        if (more) {
            const int nxt = cur ^ 1;
            uint4 ua0 = {tf32r(na0.x), tf32r(na0.y), tf32r(na0.z), tf32r(na0.w)};
            uint4 ua1 = {tf32r(na1.x), tf32r(na1.y), tf32r(na1.z), tf32r(na1.w)};
            uint4 ub0 = {tf32r(nb0.x), tf32r(nb0.y), tf32r(nb0.z), tf32r(nb0.w)};
            uint4 ub1 = {tf32r(nb1.x), tf32r(nb1.y), tf32r(nb1.z), tf32r(nb1.w)};
            *(uint4*)&sA[nxt][lrow0 * SMS + lq0] = ua0;
            *(uint4*)&sA[nxt][lrow1 * SMS + lq1] = ua1;
            *(uint4*)&sB[nxt][lrow0 * SMS + lq0] = ub0;
            *(uint4*)&sB[nxt][lrow1 * SMS + lq1] = ub1;
        }
        __syncthreads();
    }

    #pragma unroll
    for (int mi = 0; mi < 4; mi++) {
        #pragma unroll
        for (int ni = 0; ni < 4; ni++) {
            const int cc = nBase + wn + ni * 8 + 2 * t4;
            const float b0 = bias[cc], b1 = bias[cc + 1];
            #pragma unroll
            for (int h = 0; h < 2; h++) {
                const int row = mBase + wm + mi * 16 + g + h * 8;
                float v0 = acc[mi][ni][2 * h + 0] + b0;
                float v1 = acc[mi][ni][2 * h + 1] + b1;
                if (RES) {
                    const float* rr = Rs + (size_t)row * N + cc;
                    v0 += rr[0]; v1 += rr[1];
                }
                if (RELU) { v0 = fmaxf(v0, 0.0f); v1 = fmaxf(v1, 0.0f); }
                float2 o; o.x = v0; o.y = v1;
                *(float2*)(C + (size_t)row * N + cc) = o;
            }
        }
    }
}

// ===========================================================================
// Tensor-core flash attention (tf32 mma.sync)
// Block: 128 threads (4 warps), query block 128 (warp = 32 q-rows).
// K/V tiles: 64 keys. qkv row layout (1536): [s(3)][h(8)][d(64)]
// ===========================================================================
#define AQ_S 68   // stride (uint32) for Qs/Ks/Ss
#define AV_S 72   // stride for Vs (conflict-free k-varying B-frag)

__global__ void __launch_bounds__(128)
attn_mma_kernel(const float* __restrict__ qkv, float* __restrict__ out) {
    extern __shared__ uint32_t asmem[];
    uint32_t* Qs = asmem;                     // 128 x 68 (tf32 bits)
    uint32_t* Ks = Qs + 128 * AQ_S;           // 64 x 68
    uint32_t* Vs = Ks + 64 * AQ_S;            // 64 x 72
    uint32_t* Ss = Vs + 64 * AV_S;            // 128 x 68 (float -> tf32 bits)
    float* rowM = (float*)(Ss + 128 * AQ_S);  // 128
    float* rowL = rowM + 128;                 // 128
    float* rowA = rowL + 128;                 // 128

    const int t = threadIdx.x;      // 128
    const int wid = t >> 5;
    const int lid = t & 31;
    const int g = lid >> 2, t4 = lid & 3;
    const int h = blockIdx.y;
    const int qb = blockIdx.x * 128;
    const int wrow = wid * 32;

    // Load Q tile (scaled, tf32)
    for (int i = t; i < 128 * 16; i += 128) {
        int r = i >> 4, d4 = (i & 15) * 4;
        float4 q = *(const float4*)(qkv + (size_t)(qb + r) * 1536 + h * 64 + d4);
        uint32_t* dst = &Qs[r * AQ_S + d4];
        dst[0] = tf32r(q.x * 0.125f); dst[1] = tf32r(q.y * 0.125f);
        dst[2] = tf32r(q.z * 0.125f); dst[3] = tf32r(q.w * 0.125f);
    }
    rowM[t] = -1e30f;
    rowL[t] = 0.0f;

    float o[2][8][4];
    #pragma unroll
    for (int mi = 0; mi < 2; mi++)
        #pragma unroll
        for (int ni = 0; ni < 8; ni++)
            #pragma unroll
            for (int r = 0; r < 4; r++) o[mi][ni][r] = 0.0f;

    for (int kb = 0; kb < NSEQ; kb += 64) {
        __syncthreads();  // prev PV done with Ks/Vs/Ss; first iter: Q/row init done
        // Load K, V tiles (tf32)
        for (int i = t; i < 64 * 16; i += 128) {
            int r = i >> 4, d4 = (i & 15) * 4;
            const float* base = qkv + (size_t)(kb + r) * 1536 + h * 64 + d4;
            float4 kv = *(const float4*)(base + 512);
            float4 vv = *(const float4*)(base + 1024);
            uint32_t* kd = &Ks[r * AQ_S + d4];
            kd[0] = tf32r(kv.x); kd[1] = tf32r(kv.y);
            kd[2] = tf32r(kv.z); kd[3] = tf32r(kv.w);
            uint32_t* vd = &Vs[r * AV_S + d4];
            vd[0] = tf32r(vv.x); vd[1] = tf32r(vv.y);
            vd[2] = tf32r(vv.z); vd[3] = tf32r(vv.w);
        }
        __syncthreads();

        // S = Q*K^T : warp rows [wrow, wrow+32), cols 0..63
        float sf[2][8][4];
        #pragma unroll
        for (int mi = 0; mi < 2; mi++)
            #pragma unroll
            for (int ni = 0; ni < 8; ni++)
                #pragma unroll
                for (int r = 0; r < 4; r++) sf[mi][ni][r] = 0.0f;

        #pragma unroll
        for (int ks = 0; ks < 64; ks += 8) {
            uint32_t af[2][4];
            #pragma unroll
            for (int mi = 0; mi < 2; mi++) {
                int base = (wrow + mi * 16 + g) * AQ_S + ks + t4;
                af[mi][0] = Qs[base];
                af[mi][1] = Qs[base + 8 * AQ_S];
                af[mi][2] = Qs[base + 4];
                af[mi][3] = Qs[base + 8 * AQ_S + 4];
            }
            #pragma unroll
            for (int ni = 0; ni < 8; ni++) {
                uint32_t bf[2];
                int base = (ni * 8 + g) * AQ_S + ks + t4;
                bf[0] = Ks[base];
                bf[1] = Ks[base + 4];
                mma1688(sf[0][ni], af[0], bf);
                mma1688(sf[1][ni], af[1], bf);
            }
        }
        // Write S fragments to smem (float)
        #pragma unroll
        for (int mi = 0; mi < 2; mi++) {
            #pragma unroll
            for (int ni = 0; ni < 8; ni++) {
                int r0 = wrow + mi * 16 + g;
                int cc = ni * 8 + 2 * t4;
                float2 lo; lo.x = sf[mi][ni][0]; lo.y = sf[mi][ni][1];
                float2 hi; hi.x = sf[mi][ni][2]; hi.y = sf[mi][ni][3];
                *(float2*)&((float*)Ss)[r0 * AQ_S + cc] = lo;
                *(float2*)&((float*)Ss)[(r0 + 8) * AQ_S + cc] = hi;
            }
        }
        __syncthreads();

        // Online softmax: thread t owns row t; write P back as tf32 bits
        {
            float* Sr = (float*)Ss + t * AQ_S;
            uint32_t* Pr = Ss + t * AQ_S;
            float mprev = rowM[t];
            float mx = mprev;
            #pragma unroll 8
            for (int j = 0; j < 64; j++) mx = fmaxf(mx, Sr[j]);
            float al = __expf(mprev - mx);
            float sum = 0.0f;
            #pragma unroll 8
            for (int j = 0; j < 64; j++) {
                float p = __expf(Sr[j] - mx);
                sum += p;
                Pr[j] = tf32r(p);
            }
            rowL[t] = rowL[t] * al + sum;
            rowM[t] = mx;
            rowA[t] = al;
        }
        __syncthreads();

        // Rescale O by alpha, then O += P*V
        #pragma unroll
        for (int mi = 0; mi < 2; mi++) {
            float a0 = rowA[wrow + mi * 16 + g];
            float a1 = rowA[wrow + mi * 16 + g + 8];
            #pragma unroll
            for (int ni = 0; ni < 8; ni++) {
                o[mi][ni][0] *= a0; o[mi][ni][1] *= a0;
                o[mi][ni][2] *= a1; o[mi][ni][3] *= a1;
            }
        }
        #pragma unroll
        for (int ks = 0; ks < 64; ks += 8) {
            uint32_t af[2][4];
            #pragma unroll
            for (int mi = 0; mi < 2; mi++) {
                int base = (wrow + mi * 16 + g) * AQ_S + ks + t4;
                af[mi][0] = Ss[base];
                af[mi][1] = Ss[base + 8 * AQ_S];
                af[mi][2] = Ss[base + 4];
                af[mi][3] = Ss[base + 8 * AQ_S + 4];
            }
            #pragma unroll
            for (int ni = 0; ni < 8; ni++) {
                uint32_t bf[2];
                bf[0] = Vs[(ks + t4) * AV_S + ni * 8 + g];
                bf[1] = Vs[(ks + t4 + 4) * AV_S + ni * 8 + g];
                mma1688(o[0][ni], af[0], bf);
                mma1688(o[1][ni], af[1], bf);
            }
        }
    }

    // Normalize + store: out[(qb+row), h*64 + col]
    #pragma unroll
    for (int mi = 0; mi < 2; mi++) {
        float inv0 = 1.0f / rowL[wrow + mi * 16 + g];
        float inv1 = 1.0f / rowL[wrow + mi * 16 + g + 8];
        #pragma unroll
        for (int ni = 0; ni < 8; ni++) {
            int cc = h * 64 + ni * 8 + 2 * t4;
            int r0 = qb + wrow + mi * 16 + g;
            float2 lo; lo.x = o[mi][ni][0] * inv0; lo.y = o[mi][ni][1] * inv0;
            float2 hi; hi.x = o[mi][ni][2] * inv1; hi.y = o[mi][ni][3] * inv1;
            *(float2*)(out + (size_t)r0 * EDIM + cc) = lo;
            *(float2*)(out + (size_t)(r0 + 8) * EDIM + cc) = hi;
        }
    }
}

static const int ATTN_SMEM =
    (128 * AQ_S + 64 * AQ_S + 64 * AV_S + 128 * AQ_S) * 4 + 3 * 128 * 4;  // 107008 B

extern "C" void kernel_launch(void* const* d_in, const int* in_sizes, int n_in,
                              void* d_out, int out_size) {
    const float* x      = (const float*)d_in[0];
    const float* ln_g   = (const float*)d_in[1];
    const float* ln_b   = (const float*)d_in[2];
    const float* qkv_w  = (const float*)d_in[3];
    const float* qkv_b  = (const float*)d_in[4];
    const float* proj_w = (const float*)d_in[5];
    const float* proj_b = (const float*)d_in[6];
    const float* fc1_w  = (const float*)d_in[7];
    const float* fc1_b  = (const float*)d_in[8];
    const float* fc2_w  = (const float*)d_in[9];
    const float* fc2_b  = (const float*)d_in[10];
    const float* fc3_w  = (const float*)d_in[11];
    const float* fc3_b  = (const float*)d_in[12];
    float* out = (float*)d_out;

    float *h1, *qkvb, *attnb, *x1, *h2, *m1, *m2;
    cudaGetSymbolAddress((void**)&h1, g_h1);
    cudaGetSymbolAddress((void**)&qkvb, g_qkv);
    cudaGetSymbolAddress((void**)&attnb, g_attn);
    cudaGetSymbolAddress((void**)&x1, g_x1);
    cudaGetSymbolAddress((void**)&h2, g_h2);
    cudaGetSymbolAddress((void**)&m1, g_m1);
    cudaGetSymbolAddress((void**)&m2, g_m2);

    cudaFuncSetAttribute(attn_mma_kernel, cudaFuncAttributeMaxDynamicSharedMemorySize,
                         ATTN_SMEM);

    // 1. LN1
    ln_kernel<<<NSEQ, 128>>>(x, ln_g, ln_b, h1);
    // 2. QKV: [4096,512] x [1536,512]^T
    mma_gemm<false, false><<<dim3(12, 32), 256>>>(h1, qkv_w, qkv_b, nullptr, qkvb,
                                                  NSEQ, 3 * EDIM, EDIM);
    // 3. Attention (tensor core)
    attn_mma_kernel<<<dim3(32, NHEAD), 128, ATTN_SMEM>>>(qkvb, attnb);
    // 4. proj + residual
    mma_gemm<false, true><<<dim3(4, 32), 256>>>(attnb, proj_w, proj_b, x, x1,
                                                NSEQ, EDIM, EDIM);
    // 5. LN2
    ln_kernel<<<NSEQ, 128>>>(x1, ln_g, ln_b, h2);
    // 6. fc1 + relu
    mma_gemm<true, false><<<dim3(16, 32), 256>>>(h2, fc1_w, fc1_b, nullptr, m1,
                                                 NSEQ, HDIM, EDIM);
    // 7. fc2 + relu
    mma_gemm<true, false><<<dim3(16, 32), 256>>>(m1, fc2_w, fc2_b, nullptr, m2,
                                                 NSEQ, HDIM, HDIM);
    // 8. fc3 + bias + residual -> out
    mma_gemm<false, true><<<dim3(4, 32), 256>>>(m2, fc3_w, fc3_b, x1, out,
                                                NSEQ, EDIM, HDIM);
}

// round 8
// speedup vs baseline: 2.7282x; 1.0979x over previous
#include <cuda_runtime.h>
#include <cstdint>
#include <math.h>

// Problem constants
#define EDIM 512
#define NSEQ 4096
#define NHEAD 8
#define HDIM 2048

typedef unsigned long long u64;

// ---- tf32 mma.sync helpers (family-agnostic PTX, works on compute_103) ----
__device__ __forceinline__ uint32_t tf32r(float f) {
    uint32_t u;
    asm("cvt.rna.tf32.f32 %0, %1;" : "=r"(u) : "f"(f));
    return u;
}
__device__ __forceinline__ void mma1688(float* c, const uint32_t* a, const uint32_t* b) {
    asm volatile(
        "mma.sync.aligned.m16n8k8.row.col.f32.tf32.tf32.f32 "
        "{%0,%1,%2,%3}, {%4,%5,%6,%7}, {%8,%9}, {%0,%1,%2,%3};"
        : "+f"(c[0]), "+f"(c[1]), "+f"(c[2]), "+f"(c[3])
        : "r"(a[0]), "r"(a[1]), "r"(a[2]), "r"(a[3]), "r"(b[0]), "r"(b[1]));
}
__device__ __forceinline__ uint32_t smem_u32(const void* p) {
    uint32_t a;
    asm("{ .reg .u64 t; cvta.to.shared.u64 t, %1; cvt.u32.u64 %0, t; }" : "=r"(a) : "l"(p));
    return a;
}
__device__ __forceinline__ void cpa16(uint32_t s, const void* g) {
    asm volatile("cp.async.cg.shared.global [%0], [%1], 16;" :: "r"(s), "l"(g));
}
#define CP_COMMIT() asm volatile("cp.async.commit_group;" ::: "memory")
#define CP_WAIT0()  asm volatile("cp.async.wait_group 0;" ::: "memory")

// Scratch (alloc-free rule: __device__ globals)
__device__ float g_h1[NSEQ * EDIM];
__device__ float g_qkv[NSEQ * 3 * EDIM];
__device__ float g_attn[NSEQ * EDIM];
__device__ float g_x1[NSEQ * EDIM];
__device__ float g_h2[NSEQ * EDIM];
__device__ float g_m1[NSEQ * HDIM];
__device__ float g_m2[NSEQ * HDIM];

// ===========================================================================
// LayerNorm
// ===========================================================================
__global__ void ln_kernel(const float* __restrict__ X, const float* __restrict__ g,
                          const float* __restrict__ b, float* __restrict__ Y) {
    const int row = blockIdx.x;
    const int t = threadIdx.x;  // 128 threads
    const float4* Xv = (const float4*)(X + (size_t)row * EDIM);
    float4 v = Xv[t];

    __shared__ float red[4];
    float s = v.x + v.y + v.z + v.w;
    #pragma unroll
    for (int o = 16; o > 0; o >>= 1) s += __shfl_down_sync(0xffffffffu, s, o);
    if ((t & 31) == 0) red[t >> 5] = s;
    __syncthreads();
    float mean = (red[0] + red[1] + red[2] + red[3]) * (1.0f / EDIM);
    __syncthreads();

    float dx = v.x - mean, dy = v.y - mean, dz = v.z - mean, dw = v.w - mean;
    float s2 = dx * dx + dy * dy + dz * dz + dw * dw;
    #pragma unroll
    for (int o = 16; o > 0; o >>= 1) s2 += __shfl_down_sync(0xffffffffu, s2, o);
    if ((t & 31) == 0) red[t >> 5] = s2;
    __syncthreads();
    float var = (red[0] + red[1] + red[2] + red[3]) * (1.0f / EDIM);
    float rs = rsqrtf(var + 1e-5f);

    float4 gv = ((const float4*)g)[t];
    float4 bv = ((const float4*)b)[t];
    float4 o4;
    o4.x = dx * rs * gv.x + bv.x;
    o4.y = dy * rs * gv.y + bv.y;
    o4.z = dz * rs * gv.z + bv.z;
    o4.w = dw * rs * gv.w + bv.w;
    ((float4*)(Y + (size_t)row * EDIM))[t] = o4;
}

// ===========================================================================
// tf32 mma.sync GEMM: C[M,N] = A[M,K]*B[N,K]^T (+bias, +res, +relu)
// CTA 128x128, 8 warps (2x4), warp tile 64x32, K-chunk 16.
// cp.async double-buffered loader; raw fp32 bits fed to tf32 MMA (HW trunc).
// __launch_bounds__(256,2): 2 CTAs/SM for latency hiding.
// ===========================================================================
#define SMS 20   // smem row stride (floats)

template <bool RELU, bool RES>
__global__ void __launch_bounds__(256, 2)
mma_gemm(const float* __restrict__ A, const float* __restrict__ B,
         const float* __restrict__ bias, const float* __restrict__ Rs,
         float* __restrict__ C, int M, int N, int K) {
    __shared__ uint32_t sA[2][128 * SMS];
    __shared__ uint32_t sB[2][128 * SMS];

    const int t = threadIdx.x;
    const int wid = t >> 5;
    const int lid = t & 31;
    const int mBase = blockIdx.y * 128;
    const int nBase = blockIdx.x * 128;

    const int wm = (wid >> 2) * 64;   // warp row offset
    const int wn = (wid & 3) * 32;    // warp col offset
    const int g = lid >> 2;           // group id (0..7)
    const int t4 = lid & 3;           // thread in group (0..3)

    float acc[4][4][4];
    #pragma unroll
    for (int mi = 0; mi < 4; mi++)
        #pragma unroll
        for (int ni = 0; ni < 4; ni++)
            #pragma unroll
            for (int r = 0; r < 4; r++) acc[mi][ni][r] = 0.0f;

    // loader indexing: 512 float4 slots per tile (128 rows x 4 quads), 2/thread
    const int s0 = t * 2;
    const int lrow0 = s0 >> 2, lq0 = (s0 & 3) * 4;
    const int lrow1 = (s0 + 1) >> 2, lq1 = ((s0 + 1) & 3) * 4;

    const float* Ap0 = A + (size_t)(mBase + lrow0) * K + lq0;
    const float* Ap1 = A + (size_t)(mBase + lrow1) * K + lq1;
    const float* Bp0 = B + (size_t)(nBase + lrow0) * K + lq0;
    const float* Bp1 = B + (size_t)(nBase + lrow1) * K + lq1;
    const uint32_t sa0[2] = {smem_u32(&sA[0][lrow0 * SMS + lq0]),
                             smem_u32(&sA[1][lrow0 * SMS + lq0])};
    const uint32_t sa1[2] = {smem_u32(&sA[0][lrow1 * SMS + lq1]),
                             smem_u32(&sA[1][lrow1 * SMS + lq1])};
    const uint32_t sb0[2] = {smem_u32(&sB[0][lrow0 * SMS + lq0]),
                             smem_u32(&sB[1][lrow0 * SMS + lq0])};
    const uint32_t sb1[2] = {smem_u32(&sB[0][lrow1 * SMS + lq1]),
                             smem_u32(&sB[1][lrow1 * SMS + lq1])};

    auto issue_chunk = [&](int c, int buf) {
        const int k0 = c << 4;
        cpa16(sa0[buf], Ap0 + k0);
        cpa16(sa1[buf], Ap1 + k0);
        cpa16(sb0[buf], Bp0 + k0);
        cpa16(sb1[buf], Bp1 + k0);
    };

    issue_chunk(0, 0);
    CP_COMMIT();

    const int T = K >> 4;
    for (int c = 0; c < T; c++) {
        const int cur = c & 1;
        CP_WAIT0();
        __syncthreads();
        if (c + 1 < T) {
            issue_chunk(c + 1, cur ^ 1);
            CP_COMMIT();
        }

        #pragma unroll
        for (int ks = 0; ks < 16; ks += 8) {
            uint32_t af[4][4], bf[4][2];
            #pragma unroll
            for (int mi = 0; mi < 4; mi++) {
                int base = (wm + mi * 16 + g) * SMS + ks + t4;
                af[mi][0] = sA[cur][base];
                af[mi][1] = sA[cur][base + 8 * SMS];
                af[mi][2] = sA[cur][base + 4];
                af[mi][3] = sA[cur][base + 8 * SMS + 4];
            }
            #pragma unroll
            for (int ni = 0; ni < 4; ni++) {
                int base = (wn + ni * 8 + g) * SMS + ks + t4;
                bf[ni][0] = sB[cur][base];
                bf[ni][1] = sB[cur][base + 4];
            }
            #pragma unroll
            for (int mi = 0; mi < 4; mi++)
                #pragma unroll
                for (int ni = 0; ni < 4; ni++)
                    mma1688(acc[mi][ni], af[mi], bf[ni]);
        }
        __syncthreads();
    }

    // Epilogue
    #pragma unroll
    for (int mi = 0; mi < 4; mi++) {
        #pragma unroll
        for (int ni = 0; ni < 4; ni++) {
            const int cc = nBase + wn + ni * 8 + 2 * t4;
            const float b0 = bias[cc], b1 = bias[cc + 1];
            #pragma unroll
            for (int h = 0; h < 2; h++) {
                const int row = mBase + wm + mi * 16 + g + h * 8;
                float v0 = acc[mi][ni][2 * h + 0] + b0;
                float v1 = acc[mi][ni][2 * h + 1] + b1;
                if (RES) {
                    const float* rr = Rs + (size_t)row * N + cc;
                    v0 += rr[0]; v1 += rr[1];
                }
                if (RELU) { v0 = fmaxf(v0, 0.0f); v1 = fmaxf(v1, 0.0f); }
                float2 o; o.x = v0; o.y = v1;
                *(float2*)(C + (size_t)row * N + cc) = o;
            }
        }
    }
}

// ===========================================================================
// Tensor-core flash attention (tf32 mma.sync) — unchanged from R7 (passing)
// ===========================================================================
#define AQ_S 68
#define AV_S 72

__global__ void __launch_bounds__(128)
attn_mma_kernel(const float* __restrict__ qkv, float* __restrict__ out) {
    extern __shared__ uint32_t asmem[];
    uint32_t* Qs = asmem;                     // 128 x 68
    uint32_t* Ks = Qs + 128 * AQ_S;           // 64 x 68
    uint32_t* Vs = Ks + 64 * AQ_S;            // 64 x 72
    uint32_t* Ss = Vs + 64 * AV_S;            // 128 x 68
    float* rowM = (float*)(Ss + 128 * AQ_S);
    float* rowL = rowM + 128;
    float* rowA = rowL + 128;

    const int t = threadIdx.x;
    const int wid = t >> 5;
    const int lid = t & 31;
    const int g = lid >> 2, t4 = lid & 3;
    const int h = blockIdx.y;
    const int qb = blockIdx.x * 128;
    const int wrow = wid * 32;

    for (int i = t; i < 128 * 16; i += 128) {
        int r = i >> 4, d4 = (i & 15) * 4;
        float4 q = *(const float4*)(qkv + (size_t)(qb + r) * 1536 + h * 64 + d4);
        uint32_t* dst = &Qs[r * AQ_S + d4];
        dst[0] = tf32r(q.x * 0.125f); dst[1] = tf32r(q.y * 0.125f);
        dst[2] = tf32r(q.z * 0.125f); dst[3] = tf32r(q.w * 0.125f);
    }
    rowM[t] = -1e30f;
    rowL[t] = 0.0f;

    float o[2][8][4];
    #pragma unroll
    for (int mi = 0; mi < 2; mi++)
        #pragma unroll
        for (int ni = 0; ni < 8; ni++)
            #pragma unroll
            for (int r = 0; r < 4; r++) o[mi][ni][r] = 0.0f;

    for (int kb = 0; kb < NSEQ; kb += 64) {
        __syncthreads();
        for (int i = t; i < 64 * 16; i += 128) {
            int r = i >> 4, d4 = (i & 15) * 4;
            const float* base = qkv + (size_t)(kb + r) * 1536 + h * 64 + d4;
            float4 kv = *(const float4*)(base + 512);
            float4 vv = *(const float4*)(base + 1024);
            uint32_t* kd = &Ks[r * AQ_S + d4];
            kd[0] = tf32r(kv.x); kd[1] = tf32r(kv.y);
            kd[2] = tf32r(kv.z); kd[3] = tf32r(kv.w);
            uint32_t* vd = &Vs[r * AV_S + d4];
            vd[0] = tf32r(vv.x); vd[1] = tf32r(vv.y);
            vd[2] = tf32r(vv.z); vd[3] = tf32r(vv.w);
        }
        __syncthreads();

        float sf[2][8][4];
        #pragma unroll
        for (int mi = 0; mi < 2; mi++)
            #pragma unroll
            for (int ni = 0; ni < 8; ni++)
                #pragma unroll
                for (int r = 0; r < 4; r++) sf[mi][ni][r] = 0.0f;

        #pragma unroll
        for (int ks = 0; ks < 64; ks += 8) {
            uint32_t af[2][4];
            #pragma unroll
            for (int mi = 0; mi < 2; mi++) {
                int base = (wrow + mi * 16 + g) * AQ_S + ks + t4;
                af[mi][0] = Qs[base];
                af[mi][1] = Qs[base + 8 * AQ_S];
                af[mi][2] = Qs[base + 4];
                af[mi][3] = Qs[base + 8 * AQ_S + 4];
            }
            #pragma unroll
            for (int ni = 0; ni < 8; ni++) {
                uint32_t bf[2];
                int base = (ni * 8 + g) * AQ_S + ks + t4;
                bf[0] = Ks[base];
                bf[1] = Ks[base + 4];
                mma1688(sf[0][ni], af[0], bf);
                mma1688(sf[1][ni], af[1], bf);
            }
        }
        #pragma unroll
        for (int mi = 0; mi < 2; mi++) {
            #pragma unroll
            for (int ni = 0; ni < 8; ni++) {
                int r0 = wrow + mi * 16 + g;
                int cc = ni * 8 + 2 * t4;
                float2 lo; lo.x = sf[mi][ni][0]; lo.y = sf[mi][ni][1];
                float2 hi; hi.x = sf[mi][ni][2]; hi.y = sf[mi][ni][3];
                *(float2*)&((float*)Ss)[r0 * AQ_S + cc] = lo;
                *(float2*)&((float*)Ss)[(r0 + 8) * AQ_S + cc] = hi;
            }
        }
        __syncthreads();

        {
            float* Sr = (float*)Ss + t * AQ_S;
            uint32_t* Pr = Ss + t * AQ_S;
            float mprev = rowM[t];
            float mx = mprev;
            #pragma unroll 8
            for (int j = 0; j < 64; j++) mx = fmaxf(mx, Sr[j]);
            float al = __expf(mprev - mx);
            float sum = 0.0f;
            #pragma unroll 8
            for (int j = 0; j < 64; j++) {
                float p = __expf(Sr[j] - mx);
                sum += p;
                Pr[j] = tf32r(p);
            }
            rowL[t] = rowL[t] * al + sum;
            rowM[t] = mx;
            rowA[t] = al;
        }
        __syncthreads();

        #pragma unroll
        for (int mi = 0; mi < 2; mi++) {
            float a0 = rowA[wrow + mi * 16 + g];
            float a1 = rowA[wrow + mi * 16 + g + 8];
            #pragma unroll
            for (int ni = 0; ni < 8; ni++) {
                o[mi][ni][0] *= a0; o[mi][ni][1] *= a0;
                o[mi][ni][2] *= a1; o[mi][ni][3] *= a1;
            }
        }
        #pragma unroll
        for (int ks = 0; ks < 64; ks += 8) {
            uint32_t af[2][4];
            #pragma unroll
            for (int mi = 0; mi < 2; mi++) {
                int base = (wrow + mi * 16 + g) * AQ_S + ks + t4;
                af[mi][0] = Ss[base];
                af[mi][1] = Ss[base + 8 * AQ_S];
                af[mi][2] = Ss[base + 4];
                af[mi][3] = Ss[base + 8 * AQ_S + 4];
            }
            #pragma unroll
            for (int ni = 0; ni < 8; ni++) {
                uint32_t bf[2];
                bf[0] = Vs[(ks + t4) * AV_S + ni * 8 + g];
                bf[1] = Vs[(ks + t4 + 4) * AV_S + ni * 8 + g];
                mma1688(o[0][ni], af[0], bf);
                mma1688(o[1][ni], af[1], bf);
            }
        }
    }

    #pragma unroll
    for (int mi = 0; mi < 2; mi++) {
        float inv0 = 1.0f / rowL[wrow + mi * 16 + g];
        float inv1 = 1.0f / rowL[wrow + mi * 16 + g + 8];
        #pragma unroll
        for (int ni = 0; ni < 8; ni++) {
            int cc = h * 64 + ni * 8 + 2 * t4;
            int r0 = qb + wrow + mi * 16 + g;
            float2 lo; lo.x = o[mi][ni][0] * inv0; lo.y = o[mi][ni][1] * inv0;
            float2 hi; hi.x = o[mi][ni][2] * inv1; hi.y = o[mi][ni][3] * inv1;
            *(float2*)(out + (size_t)r0 * EDIM + cc) = lo;
            *(float2*)(out + (size_t)(r0 + 8) * EDIM + cc) = hi;
        }
    }
}

static const int ATTN_SMEM =
    (128 * AQ_S + 64 * AQ_S + 64 * AV_S + 128 * AQ_S) * 4 + 3 * 128 * 4;

extern "C" void kernel_launch(void* const* d_in, const int* in_sizes, int n_in,
                              void* d_out, int out_size) {
    const float* x      = (const float*)d_in[0];
    const float* ln_g   = (const float*)d_in[1];
    const float* ln_b   = (const float*)d_in[2];
    const float* qkv_w  = (const float*)d_in[3];
    const float* qkv_b  = (const float*)d_in[4];
    const float* proj_w = (const float*)d_in[5];
    const float* proj_b = (const float*)d_in[6];
    const float* fc1_w  = (const float*)d_in[7];
    const float* fc1_b  = (const float*)d_in[8];
    const float* fc2_w  = (const float*)d_in[9];
    const float* fc2_b  = (const float*)d_in[10];
    const float* fc3_w  = (const float*)d_in[11];
    const float* fc3_b  = (const float*)d_in[12];
    float* out = (float*)d_out;

    float *h1, *qkvb, *attnb, *x1, *h2, *m1, *m2;
    cudaGetSymbolAddress((void**)&h1, g_h1);
    cudaGetSymbolAddress((void**)&qkvb, g_qkv);
    cudaGetSymbolAddress((void**)&attnb, g_attn);
    cudaGetSymbolAddress((void**)&x1, g_x1);
    cudaGetSymbolAddress((void**)&h2, g_h2);
    cudaGetSymbolAddress((void**)&m1, g_m1);
    cudaGetSymbolAddress((void**)&m2, g_m2);

    cudaFuncSetAttribute(attn_mma_kernel, cudaFuncAttributeMaxDynamicSharedMemorySize,
                         ATTN_SMEM);

    // 1. LN1
    ln_kernel<<<NSEQ, 128>>>(x, ln_g, ln_b, h1);
    // 2. QKV: [4096,512] x [1536,512]^T
    mma_gemm<false, false><<<dim3(12, 32), 256>>>(h1, qkv_w, qkv_b, nullptr, qkvb,
                                                  NSEQ, 3 * EDIM, EDIM);
    // 3. Attention (tensor core)
    attn_mma_kernel<<<dim3(32, NHEAD), 128, ATTN_SMEM>>>(qkvb, attnb);
    // 4. proj + residual
    mma_gemm<false, true><<<dim3(4, 32), 256>>>(attnb, proj_w, proj_b, x, x1,
                                                NSEQ, EDIM, EDIM);
    // 5. LN2
    ln_kernel<<<NSEQ, 128>>>(x1, ln_g, ln_b, h2);
    // 6. fc1 + relu
    mma_gemm<true, false><<<dim3(16, 32), 256>>>(h2, fc1_w, fc1_b, nullptr, m1,
                                                 NSEQ, HDIM, EDIM);
    // 7. fc2 + relu
    mma_gemm<true, false><<<dim3(16, 32), 256>>>(m1, fc2_w, fc2_b, nullptr, m2,
                                                 NSEQ, HDIM, HDIM);
    // 8. fc3 + bias + residual -> out
    mma_gemm<false, true><<<dim3(4, 32), 256>>>(m2, fc3_w, fc3_b, x1, out,
                                                NSEQ, EDIM, HDIM);
}